// round 9
// baseline (speedup 1.0000x reference)
#include <cuda_runtime.h>
#include <cuda_bf16.h>
#include <cstdint>
#include <math.h>

#define NUM_USERS 8192
#define NUM_ITEMS 32768
#define FEAT      129
#define KSEG      144              // one split segment, padded to mult of 16
#define KCAT      448              // 3*KSEG = 432, padded to 7 chunks of 64
#define KCHUNKS   7
#define BM        128
#define BN        256
#define BK        64
#define NTHREADS  256              // 8 warps, each 64x64

// ---- scratch (__device__ globals: allocation-free) ----
__device__ __align__(128) __nv_bfloat16 g_Abf[(size_t)NUM_USERS * KCAT];  // [Ahi|Ahi|Alo|pad0]
__device__ __align__(128) __nv_bfloat16 g_Bbf[(size_t)NUM_ITEMS * KCAT];  // [Bhi|Blo|Bhi|pad0]

__device__ __forceinline__ uint32_t smem_u32(const void* p) {
    uint32_t a;
    asm("{ .reg .u64 t; cvta.to.shared.u64 t, %1; cvt.u32.u64 %0, t; }" : "=r"(a) : "l"(p));
    return a;
}

// ---- prep: fold sign, split fp32 -> (hi, lo) bf16, build concatenated-K operands ----
__global__ void prep_kernel(const float* __restrict__ h) {
    int idx = blockIdx.x * blockDim.x + threadIdx.x;
    const int totA = NUM_USERS * KSEG;
    const int totB = NUM_ITEMS * KSEG;
    const int totP = (NUM_USERS + NUM_ITEMS) * (KCAT - 3 * KSEG);  // zero pad cols 432..447
    if (idx < totA) {
        int u = idx / KSEG, k = idx - u * KSEG;
        float a = (k < FEAT) ? h[(size_t)u * FEAT + k] : 0.0f;
        __nv_bfloat16 hi = __float2bfloat16(a);
        __nv_bfloat16 lo = __float2bfloat16(a - __bfloat162float(hi));
        __nv_bfloat16* row = g_Abf + (size_t)u * KCAT;
        row[k] = hi; row[KSEG + k] = hi; row[2 * KSEG + k] = lo;
    } else if (idx < totA + totB) {
        int j = idx - totA;
        int i = j / KSEG, k = j - i * KSEG;
        float b = (k < FEAT) ? h[(size_t)(NUM_USERS + i) * FEAT + k] : 0.0f;
        if (k == 0) b = -b;  // sign fold
        __nv_bfloat16 hi = __float2bfloat16(b);
        __nv_bfloat16 lo = __float2bfloat16(b - __bfloat162float(hi));
        __nv_bfloat16* row = g_Bbf + (size_t)i * KCAT;
        row[k] = hi; row[KSEG + k] = lo; row[2 * KSEG + k] = hi;
    } else if (idx < totA + totB + totP) {
        int j = idx - totA - totB;
        int r = j / 16, k = 432 + (j - r * 16);
        __nv_bfloat16 z = __float2bfloat16(0.0f);
        if (r < NUM_USERS) g_Abf[(size_t)r * KCAT + k] = z;
        else g_Bbf[(size_t)(r - NUM_USERS) * KCAT + k] = z;
    }
}

// smem stage: A 16KB + B 32KB = 48KB; 3 stages = 144KB dynamic
#define ST_BYTES 49152
#define SB_OFF   16384
#define SM_SIZE  147456

__global__ __launch_bounds__(NTHREADS)
void gemm_mma_kernel(float* __restrict__ out) {
    extern __shared__ __align__(1024) char smem[];
    const uint32_t sb = smem_u32(smem);
    const int tid = threadIdx.x;
    const int wid = tid >> 5;
    const int L = tid & 31;
    const int m0 = blockIdx.x * BM;
    const int n0 = blockIdx.y * BN;
    const int mb = (wid & 1) * 64;    // 2 warps in m
    const int nb = (wid >> 1) * 64;   // 4 warps in n

    float acc[4][8][4];               // 128 fp32 accum per lane (64x64 warp tile)
    #pragma unroll
    for (int mi = 0; mi < 4; mi++)
        #pragma unroll
        for (int ni = 0; ni < 8; ni++)
            #pragma unroll
            for (int r = 0; r < 4; r++) acc[mi][ni][r] = 0.0f;

    // per-lane ldmatrix addressing (SW128 swizzle: XOR = (row&7)*16)
    const uint32_t xorv = (L & 7) * 16;
    const uint32_t kha = (L >> 4) * 16;          // A: k-half select from lane
    const uint32_t khb = ((L >> 3) & 1) * 16;    // B: k-half select from lane
    uint32_t aBase[4], bBase[4];
    #pragma unroll
    for (int mi = 0; mi < 4; mi++)
        aBase[mi] = (uint32_t)(mb + mi * 16 + (L & 7) + ((L >> 3) & 1) * 8) * 128;
    #pragma unroll
    for (int p = 0; p < 4; p++)
        bBase[p] = (uint32_t)(nb + p * 16 + (L & 7) + ((L >> 4) & 1) * 8) * 128;

    // cooperative cp.async chunk loader (64 bf16 K-cols; A 128 rows, B 256 rows)
    auto load_chunk = [&](int c, int stg) {
        const uint32_t base = sb + stg * ST_BYTES;
        const size_t kbase = (size_t)c * BK;
        #pragma unroll
        for (int it = 0; it < 4; it++) {                 // A: 1024 x 16B
            int idx = tid + it * NTHREADS;
            int row = idx >> 3, k8 = idx & 7;
            const void* src = g_Abf + (size_t)(m0 + row) * KCAT + kbase + k8 * 8;
            uint32_t off = row * 128 + k8 * 16;
            uint32_t dst = base + (off ^ ((off >> 3) & 0x70));
            asm volatile("cp.async.cg.shared.global [%0], [%1], 16;" :: "r"(dst), "l"(src));
        }
        #pragma unroll
        for (int it = 0; it < 8; it++) {                 // B: 2048 x 16B
            int idx = tid + it * NTHREADS;
            int row = idx >> 3, k8 = idx & 7;
            const void* src = g_Bbf + (size_t)(n0 + row) * KCAT + kbase + k8 * 8;
            uint32_t off = row * 128 + k8 * 16;
            uint32_t dst = base + SB_OFF + (off ^ ((off >> 3) & 0x70));
            asm volatile("cp.async.cg.shared.global [%0], [%1], 16;" :: "r"(dst), "l"(src));
        }
        asm volatile("cp.async.commit_group;" ::: "memory");
    };

    // fragment loaders (double-buffered across k16 steps)
    uint32_t af[2][4][4], bf[2][4][4];   // bf[buf][p][..] -> b[2p],b[2p+1]
    auto load_frags = [&](int stg, int ks, int buf) {
        const uint32_t stA = sb + stg * ST_BYTES;
        const uint32_t stB = stA + SB_OFF;
        #pragma unroll
        for (int mi = 0; mi < 4; mi++) {
            uint32_t addr = stA + aBase[mi] + (((uint32_t)ks * 32 + kha) ^ xorv);
            asm volatile("ldmatrix.sync.aligned.m8n8.x4.shared.b16 {%0,%1,%2,%3}, [%4];"
                : "=r"(af[buf][mi][0]), "=r"(af[buf][mi][1]),
                  "=r"(af[buf][mi][2]), "=r"(af[buf][mi][3]) : "r"(addr));
        }
        #pragma unroll
        for (int p = 0; p < 4; p++) {
            uint32_t addr = stB + bBase[p] + (((uint32_t)ks * 32 + khb) ^ xorv);
            asm volatile("ldmatrix.sync.aligned.m8n8.x4.shared.b16 {%0,%1,%2,%3}, [%4];"
                : "=r"(bf[buf][p][0]), "=r"(bf[buf][p][1]),
                  "=r"(bf[buf][p][2]), "=r"(bf[buf][p][3]) : "r"(addr));
        }
    };
    auto mma_step = [&](int buf) {
        #pragma unroll
        for (int mi = 0; mi < 4; mi++)
            #pragma unroll
            for (int ni = 0; ni < 8; ni++) {
                const uint32_t* bb = &bf[buf][ni >> 1][(ni & 1) * 2];
                asm volatile(
                    "mma.sync.aligned.m16n8k16.row.col.f32.bf16.bf16.f32 "
                    "{%0,%1,%2,%3}, {%4,%5,%6,%7}, {%8,%9}, {%0,%1,%2,%3};"
                    : "+f"(acc[mi][ni][0]), "+f"(acc[mi][ni][1]),
                      "+f"(acc[mi][ni][2]), "+f"(acc[mi][ni][3])
                    : "r"(af[buf][mi][0]), "r"(af[buf][mi][1]),
                      "r"(af[buf][mi][2]), "r"(af[buf][mi][3]),
                      "r"(bb[0]), "r"(bb[1]));
            }
    };

    // 3-stage pipeline prologue
    load_chunk(0, 0);
    load_chunk(1, 1);

    for (int ch = 0; ch < KCHUNKS; ch++) {
        const int stg = ch % 3;
        if (ch >= KCHUNKS - 2) {
            asm volatile("cp.async.wait_group 0;" ::: "memory");
        } else {
            asm volatile("cp.async.wait_group 1;" ::: "memory");
        }
        __syncthreads();
        if (ch + 2 < KCHUNKS) load_chunk(ch + 2, (ch + 2) % 3);

        load_frags(stg, 0, 0);
        #pragma unroll
        for (int ks = 0; ks < 4; ks++) {
            if (ks < 3) load_frags(stg, ks + 1, (ks + 1) & 1);
            mma_step(ks & 1);
        }
        __syncthreads();   // all warps done with stage stg before it is overwritten
    }

    // ---- fused epilogue: theta=max(-d, 1+1e-7); out = -min(acosh(theta)^2, 50) ----
    const float THMIN = 1.00000011920928955f;  // fp32(1 + 1e-7), identical to jnp
    const float LN2 = 0.69314718055994531f;
    #pragma unroll
    for (int mi = 0; mi < 4; mi++) {
        const int r0 = m0 + mb + mi * 16 + (L >> 2);
        #pragma unroll
        for (int ni = 0; ni < 8; ni++) {
            const int col = n0 + nb + ni * 8 + (L & 3) * 2;
            float v[4];
            #pragma unroll
            for (int r = 0; r < 4; r++) {
                float th = fmaxf(-acc[mi][ni][r], THMIN);
                float x = fmaf(th, th, -1.0f);
                float sq; asm("sqrt.approx.f32 %0, %1;" : "=f"(sq) : "f"(x));
                float lg; asm("lg2.approx.f32 %0, %1;" : "=f"(lg) : "f"(th + sq));
                float s = lg * LN2;
                v[r] = -fminf(s * s, 50.0f);
            }
            *(float2*)(out + (size_t)r0 * NUM_ITEMS + col)       = make_float2(v[0], v[1]);
            *(float2*)(out + (size_t)(r0 + 8) * NUM_ITEMS + col) = make_float2(v[2], v[3]);
        }
    }
}

extern "C" void kernel_launch(void* const* d_in, const int* in_sizes, int n_in,
                              void* d_out, int out_size) {
    const float* h = (const float*)d_in[0];
    float* out = (float*)d_out;

    const int totPrep = (NUM_USERS + NUM_ITEMS) * KSEG + (NUM_USERS + NUM_ITEMS) * 16;
    prep_kernel<<<(totPrep + 255) / 256, 256>>>(h);

    cudaFuncSetAttribute(gemm_mma_kernel, cudaFuncAttributeMaxDynamicSharedMemorySize, SM_SIZE);
    dim3 grid(NUM_USERS / BM, NUM_ITEMS / BN);  // (64, 128)
    gemm_mma_kernel<<<grid, NTHREADS, SM_SIZE>>>(out);
}

// round 10
// speedup vs baseline: 1.1433x; 1.1433x over previous
#include <cuda_runtime.h>
#include <cuda_bf16.h>
#include <cstdint>
#include <math.h>

#define NUM_USERS 8192
#define NUM_ITEMS 32768
#define FEAT      129
#define KSEG      144              // one split segment, padded to mult of 16
#define KCAT      448              // 3*KSEG = 432, padded to 7 chunks of 64
#define KCHUNKS   7
#define BM        128
#define BN        128
#define BK        64
#define NTHREADS  256              // 8 warps, each 64x32

// ---- scratch (__device__ globals: allocation-free) ----
__device__ __align__(128) __nv_bfloat16 g_Abf[(size_t)NUM_USERS * KCAT];  // [Ahi|Ahi|Alo|pad0]
__device__ __align__(128) __nv_bfloat16 g_Bbf[(size_t)NUM_ITEMS * KCAT];  // [Bhi|Blo|Bhi|pad0]

__device__ __forceinline__ uint32_t smem_u32(const void* p) {
    uint32_t a;
    asm("{ .reg .u64 t; cvta.to.shared.u64 t, %1; cvt.u32.u64 %0, t; }" : "=r"(a) : "l"(p));
    return a;
}

// ---- prep: fold sign, split fp32 -> (hi, lo) bf16, build concatenated-K operands ----
__global__ void prep_kernel(const float* __restrict__ h) {
    int idx = blockIdx.x * blockDim.x + threadIdx.x;
    const int totA = NUM_USERS * KSEG;
    const int totB = NUM_ITEMS * KSEG;
    const int totP = (NUM_USERS + NUM_ITEMS) * (KCAT - 3 * KSEG);  // zero pad cols 432..447
    if (idx < totA) {
        int u = idx / KSEG, k = idx - u * KSEG;
        float a = (k < FEAT) ? h[(size_t)u * FEAT + k] : 0.0f;
        __nv_bfloat16 hi = __float2bfloat16(a);
        __nv_bfloat16 lo = __float2bfloat16(a - __bfloat162float(hi));
        __nv_bfloat16* row = g_Abf + (size_t)u * KCAT;
        row[k] = hi; row[KSEG + k] = hi; row[2 * KSEG + k] = lo;
    } else if (idx < totA + totB) {
        int j = idx - totA;
        int i = j / KSEG, k = j - i * KSEG;
        float b = (k < FEAT) ? h[(size_t)(NUM_USERS + i) * FEAT + k] : 0.0f;
        if (k == 0) b = -b;  // sign fold
        __nv_bfloat16 hi = __float2bfloat16(b);
        __nv_bfloat16 lo = __float2bfloat16(b - __bfloat162float(hi));
        __nv_bfloat16* row = g_Bbf + (size_t)i * KCAT;
        row[k] = hi; row[KSEG + k] = lo; row[2 * KSEG + k] = hi;
    } else if (idx < totA + totB + totP) {
        int j = idx - totA - totB;
        int r = j / 16, k = 432 + (j - r * 16);
        __nv_bfloat16 z = __float2bfloat16(0.0f);
        if (r < NUM_USERS) g_Abf[(size_t)r * KCAT + k] = z;
        else g_Bbf[(size_t)(r - NUM_USERS) * KCAT + k] = z;
    }
}

// smem stage: A 16KB + B 16KB = 32KB; 3 stages = 96KB dynamic (2 CTAs/SM = 192KB)
#define ST_BYTES 32768
#define SB_OFF   16384
#define SM_SIZE  98304

__global__ __launch_bounds__(NTHREADS, 2)
void gemm_mma_kernel(float* __restrict__ out) {
    extern __shared__ __align__(1024) char smem[];
    const uint32_t sb = smem_u32(smem);
    const int tid = threadIdx.x;
    const int wid = tid >> 5;
    const int L = tid & 31;
    const int m0 = blockIdx.x * BM;
    const int n0 = blockIdx.y * BN;
    const int mb = (wid & 1) * 64;    // 2 warps in m
    const int nb = (wid >> 1) * 32;   // 4 warps in n

    float acc[4][4][4];               // 64 fp32 accum per lane (64x32 warp tile)
    #pragma unroll
    for (int mi = 0; mi < 4; mi++)
        #pragma unroll
        for (int ni = 0; ni < 4; ni++)
            #pragma unroll
            for (int r = 0; r < 4; r++) acc[mi][ni][r] = 0.0f;

    // per-lane ldmatrix addressing (SW128 swizzle: XOR = (row&7)*16)
    const uint32_t xorv = (L & 7) * 16;
    const uint32_t kha = (L >> 4) * 16;          // A: k-half select from lane
    const uint32_t khb = ((L >> 3) & 1) * 16;    // B: k-half select from lane
    uint32_t aBase[4], bBase[2];
    #pragma unroll
    for (int mi = 0; mi < 4; mi++)
        aBase[mi] = (uint32_t)(mb + mi * 16 + (L & 7) + ((L >> 3) & 1) * 8) * 128;
    #pragma unroll
    for (int p = 0; p < 2; p++)
        bBase[p] = (uint32_t)(nb + p * 16 + (L & 7) + ((L >> 4) & 1) * 8) * 128;

    // cooperative cp.async chunk loader (64 bf16 K-cols; A 128 rows, B 128 rows)
    auto load_chunk = [&](int c, int stg) {
        const uint32_t base = sb + stg * ST_BYTES;
        const size_t kbase = (size_t)c * BK;
        #pragma unroll
        for (int it = 0; it < 4; it++) {                 // A: 1024 x 16B
            int idx = tid + it * NTHREADS;
            int row = idx >> 3, k8 = idx & 7;
            const void* src = g_Abf + (size_t)(m0 + row) * KCAT + kbase + k8 * 8;
            uint32_t off = row * 128 + k8 * 16;
            uint32_t dst = base + (off ^ ((off >> 3) & 0x70));
            asm volatile("cp.async.cg.shared.global [%0], [%1], 16;" :: "r"(dst), "l"(src));
        }
        #pragma unroll
        for (int it = 0; it < 4; it++) {                 // B: 1024 x 16B
            int idx = tid + it * NTHREADS;
            int row = idx >> 3, k8 = idx & 7;
            const void* src = g_Bbf + (size_t)(n0 + row) * KCAT + kbase + k8 * 8;
            uint32_t off = row * 128 + k8 * 16;
            uint32_t dst = base + SB_OFF + (off ^ ((off >> 3) & 0x70));
            asm volatile("cp.async.cg.shared.global [%0], [%1], 16;" :: "r"(dst), "l"(src));
        }
        asm volatile("cp.async.commit_group;" ::: "memory");
    };

    // 3-stage pipeline prologue
    load_chunk(0, 0);
    load_chunk(1, 1);

    for (int ch = 0; ch < KCHUNKS; ch++) {
        const int stg = ch % 3;
        if (ch >= KCHUNKS - 2) {
            asm volatile("cp.async.wait_group 0;" ::: "memory");
        } else {
            asm volatile("cp.async.wait_group 1;" ::: "memory");
        }
        __syncthreads();
        if (ch + 2 < KCHUNKS) load_chunk(ch + 2, (ch + 2) % 3);

        const uint32_t stA = sb + stg * ST_BYTES;
        const uint32_t stB = stA + SB_OFF;
        #pragma unroll
        for (int ks = 0; ks < 4; ks++) {
            uint32_t a[4][4], b[4][2];
            #pragma unroll
            for (int mi = 0; mi < 4; mi++) {
                uint32_t addr = stA + aBase[mi] + (((uint32_t)ks * 32 + kha) ^ xorv);
                asm volatile("ldmatrix.sync.aligned.m8n8.x4.shared.b16 {%0,%1,%2,%3}, [%4];"
                    : "=r"(a[mi][0]), "=r"(a[mi][1]), "=r"(a[mi][2]), "=r"(a[mi][3]) : "r"(addr));
            }
            #pragma unroll
            for (int p = 0; p < 2; p++) {
                uint32_t addr = stB + bBase[p] + (((uint32_t)ks * 32 + khb) ^ xorv);
                asm volatile("ldmatrix.sync.aligned.m8n8.x4.shared.b16 {%0,%1,%2,%3}, [%4];"
                    : "=r"(b[2 * p][0]), "=r"(b[2 * p][1]), "=r"(b[2 * p + 1][0]), "=r"(b[2 * p + 1][1])
                    : "r"(addr));
            }
            #pragma unroll
            for (int mi = 0; mi < 4; mi++)
                #pragma unroll
                for (int ni = 0; ni < 4; ni++) {
                    asm volatile(
                        "mma.sync.aligned.m16n8k16.row.col.f32.bf16.bf16.f32 "
                        "{%0,%1,%2,%3}, {%4,%5,%6,%7}, {%8,%9}, {%0,%1,%2,%3};"
                        : "+f"(acc[mi][ni][0]), "+f"(acc[mi][ni][1]),
                          "+f"(acc[mi][ni][2]), "+f"(acc[mi][ni][3])
                        : "r"(a[mi][0]), "r"(a[mi][1]), "r"(a[mi][2]), "r"(a[mi][3]),
                          "r"(b[ni][0]), "r"(b[ni][1]));
                }
        }
        __syncthreads();   // all warps done with stage stg before it is overwritten
    }

    // ---- fused epilogue: theta=max(-d, 1+1e-7); out = -min(acosh(theta)^2, 50) ----
    const float THMIN = 1.00000011920928955f;  // fp32(1 + 1e-7), identical to jnp
    const float LN2 = 0.69314718055994531f;
    #pragma unroll
    for (int mi = 0; mi < 4; mi++) {
        const int r0 = m0 + mb + mi * 16 + (L >> 2);
        #pragma unroll
        for (int ni = 0; ni < 4; ni++) {
            const int col = n0 + nb + ni * 8 + (L & 3) * 2;
            float v[4];
            #pragma unroll
            for (int r = 0; r < 4; r++) {
                float th = fmaxf(-acc[mi][ni][r], THMIN);
                float x = fmaf(th, th, -1.0f);
                float sq; asm("sqrt.approx.f32 %0, %1;" : "=f"(sq) : "f"(x));
                float lg; asm("lg2.approx.f32 %0, %1;" : "=f"(lg) : "f"(th + sq));
                float s = lg * LN2;
                v[r] = -fminf(s * s, 50.0f);
            }
            *(float2*)(out + (size_t)r0 * NUM_ITEMS + col)       = make_float2(v[0], v[1]);
            *(float2*)(out + (size_t)(r0 + 8) * NUM_ITEMS + col) = make_float2(v[2], v[3]);
        }
    }
}

extern "C" void kernel_launch(void* const* d_in, const int* in_sizes, int n_in,
                              void* d_out, int out_size) {
    const float* h = (const float*)d_in[0];
    float* out = (float*)d_out;

    const int totPrep = (NUM_USERS + NUM_ITEMS) * KSEG + (NUM_USERS + NUM_ITEMS) * 16;
    prep_kernel<<<(totPrep + 255) / 256, 256>>>(h);

    cudaFuncSetAttribute(gemm_mma_kernel, cudaFuncAttributeMaxDynamicSharedMemorySize, SM_SIZE);
    dim3 grid(NUM_USERS / BM, NUM_ITEMS / BN);  // (64, 256)
    gemm_mma_kernel<<<grid, NTHREADS, SM_SIZE>>>(out);
}

// round 11
// speedup vs baseline: 1.2064x; 1.0552x over previous
#include <cuda_runtime.h>
#include <cuda_bf16.h>
#include <cstdint>
#include <math.h>

#define NUM_USERS 8192
#define NUM_ITEMS 32768
#define FEAT      129
#define KSEG      144              // one split segment, padded to mult of 16
#define KCAT      448              // 3*KSEG = 432, padded to 7 chunks of 64
#define KCHUNKS   7
#define BM        128
#define BN        128
#define BK        64
#define NTHREADS  128              // 4 warps, each 64x64

// ---- scratch (__device__ globals: allocation-free) ----
__device__ __align__(128) __nv_bfloat16 g_Abf[(size_t)NUM_USERS * KCAT];  // [Ahi|Ahi|Alo|pad0]
__device__ __align__(128) __nv_bfloat16 g_Bbf[(size_t)NUM_ITEMS * KCAT];  // [Bhi|Blo|Bhi|pad0]

__device__ __forceinline__ uint32_t smem_u32(const void* p) {
    uint32_t a;
    asm("{ .reg .u64 t; cvta.to.shared.u64 t, %1; cvt.u32.u64 %0, t; }" : "=r"(a) : "l"(p));
    return a;
}

// ---- prep: fold sign, split fp32 -> (hi, lo) bf16, build concatenated-K operands ----
__global__ void prep_kernel(const float* __restrict__ h) {
    int idx = blockIdx.x * blockDim.x + threadIdx.x;
    const int totA = NUM_USERS * KSEG;
    const int totB = NUM_ITEMS * KSEG;
    const int totP = (NUM_USERS + NUM_ITEMS) * (KCAT - 3 * KSEG);  // zero pad cols 432..447
    if (idx < totA) {
        int u = idx / KSEG, k = idx - u * KSEG;
        float a = (k < FEAT) ? h[(size_t)u * FEAT + k] : 0.0f;
        __nv_bfloat16 hi = __float2bfloat16(a);
        __nv_bfloat16 lo = __float2bfloat16(a - __bfloat162float(hi));
        __nv_bfloat16* row = g_Abf + (size_t)u * KCAT;
        row[k] = hi; row[KSEG + k] = hi; row[2 * KSEG + k] = lo;
    } else if (idx < totA + totB) {
        int j = idx - totA;
        int i = j / KSEG, k = j - i * KSEG;
        float b = (k < FEAT) ? h[(size_t)(NUM_USERS + i) * FEAT + k] : 0.0f;
        if (k == 0) b = -b;  // sign fold
        __nv_bfloat16 hi = __float2bfloat16(b);
        __nv_bfloat16 lo = __float2bfloat16(b - __bfloat162float(hi));
        __nv_bfloat16* row = g_Bbf + (size_t)i * KCAT;
        row[k] = hi; row[KSEG + k] = lo; row[2 * KSEG + k] = hi;
    } else if (idx < totA + totB + totP) {
        int j = idx - totA - totB;
        int r = j / 16, k = 432 + (j - r * 16);
        __nv_bfloat16 z = __float2bfloat16(0.0f);
        if (r < NUM_USERS) g_Abf[(size_t)r * KCAT + k] = z;
        else g_Bbf[(size_t)(r - NUM_USERS) * KCAT + k] = z;
    }
}

// smem stage: A 16KB + B 16KB = 32KB; 3 stages = 96KB dynamic (2 CTAs/SM = 192KB)
#define ST_BYTES 32768
#define SB_OFF   16384
#define SM_SIZE  98304

__global__ __launch_bounds__(NTHREADS, 2)
void gemm_mma_kernel(float* __restrict__ out) {
    extern __shared__ __align__(1024) char smem[];
    const uint32_t sb = smem_u32(smem);
    const int tid = threadIdx.x;
    const int wid = tid >> 5;
    const int L = tid & 31;
    const int m0 = blockIdx.x * BM;
    const int n0 = blockIdx.y * BN;
    const int mb = (wid & 1) * 64;    // 2 warps in m
    const int nb = (wid >> 1) * 64;   // 2 warps in n

    float acc[4][8][4];               // 128 fp32 accum per lane (64x64 warp tile)
    #pragma unroll
    for (int mi = 0; mi < 4; mi++)
        #pragma unroll
        for (int ni = 0; ni < 8; ni++)
            #pragma unroll
            for (int r = 0; r < 4; r++) acc[mi][ni][r] = 0.0f;

    // per-lane ldmatrix addressing (SW128 swizzle: XOR = (row&7)*16)
    const uint32_t xorv = (L & 7) * 16;
    const uint32_t kha = (L >> 4) * 16;          // A: k-half select from lane
    const uint32_t khb = ((L >> 3) & 1) * 16;    // B: k-half select from lane
    uint32_t aBase[4], bBase[4];
    #pragma unroll
    for (int mi = 0; mi < 4; mi++)
        aBase[mi] = (uint32_t)(mb + mi * 16 + (L & 7) + ((L >> 3) & 1) * 8) * 128;
    #pragma unroll
    for (int p = 0; p < 4; p++)
        bBase[p] = (uint32_t)(nb + p * 16 + (L & 7) + ((L >> 4) & 1) * 8) * 128;

    // cooperative cp.async chunk loader (64 bf16 K-cols; A 128 rows, B 128 rows)
    auto load_chunk = [&](int c, int stg) {
        const uint32_t base = sb + stg * ST_BYTES;
        const size_t kbase = (size_t)c * BK;
        #pragma unroll
        for (int it = 0; it < 8; it++) {                 // A: 1024 x 16B
            int idx = tid + it * NTHREADS;
            int row = idx >> 3, k8 = idx & 7;
            const void* src = g_Abf + (size_t)(m0 + row) * KCAT + kbase + k8 * 8;
            uint32_t off = row * 128 + k8 * 16;
            uint32_t dst = base + (off ^ ((off >> 3) & 0x70));
            asm volatile("cp.async.cg.shared.global [%0], [%1], 16;" :: "r"(dst), "l"(src));
        }
        #pragma unroll
        for (int it = 0; it < 8; it++) {                 // B: 1024 x 16B
            int idx = tid + it * NTHREADS;
            int row = idx >> 3, k8 = idx & 7;
            const void* src = g_Bbf + (size_t)(n0 + row) * KCAT + kbase + k8 * 8;
            uint32_t off = row * 128 + k8 * 16;
            uint32_t dst = base + SB_OFF + (off ^ ((off >> 3) & 0x70));
            asm volatile("cp.async.cg.shared.global [%0], [%1], 16;" :: "r"(dst), "l"(src));
        }
        asm volatile("cp.async.commit_group;" ::: "memory");
    };

    // fragment buffers (double-buffered across k16 steps)
    uint32_t af[2][4][4], bf[2][4][4];   // bf[buf][p][..] -> b pair (2p, 2p+1)
    auto load_frags = [&](int stg, int ks, int buf) {
        const uint32_t stA = sb + stg * ST_BYTES;
        const uint32_t stB = stA + SB_OFF;
        #pragma unroll
        for (int mi = 0; mi < 4; mi++) {
            uint32_t addr = stA + aBase[mi] + (((uint32_t)ks * 32 + kha) ^ xorv);
            asm volatile("ldmatrix.sync.aligned.m8n8.x4.shared.b16 {%0,%1,%2,%3}, [%4];"
                : "=r"(af[buf][mi][0]), "=r"(af[buf][mi][1]),
                  "=r"(af[buf][mi][2]), "=r"(af[buf][mi][3]) : "r"(addr));
        }
        #pragma unroll
        for (int p = 0; p < 4; p++) {
            uint32_t addr = stB + bBase[p] + (((uint32_t)ks * 32 + khb) ^ xorv);
            asm volatile("ldmatrix.sync.aligned.m8n8.x4.shared.b16 {%0,%1,%2,%3}, [%4];"
                : "=r"(bf[buf][p][0]), "=r"(bf[buf][p][1]),
                  "=r"(bf[buf][p][2]), "=r"(bf[buf][p][3]) : "r"(addr));
        }
    };
    auto mma_step = [&](int buf) {
        #pragma unroll
        for (int mi = 0; mi < 4; mi++)
            #pragma unroll
            for (int ni = 0; ni < 8; ni++) {
                const uint32_t* bb = &bf[buf][ni >> 1][(ni & 1) * 2];
                asm volatile(
                    "mma.sync.aligned.m16n8k16.row.col.f32.bf16.bf16.f32 "
                    "{%0,%1,%2,%3}, {%4,%5,%6,%7}, {%8,%9}, {%0,%1,%2,%3};"
                    : "+f"(acc[mi][ni][0]), "+f"(acc[mi][ni][1]),
                      "+f"(acc[mi][ni][2]), "+f"(acc[mi][ni][3])
                    : "r"(af[buf][mi][0]), "r"(af[buf][mi][1]),
                      "r"(af[buf][mi][2]), "r"(af[buf][mi][3]),
                      "r"(bb[0]), "r"(bb[1]));
            }
    };

    // 3-stage pipeline prologue
    load_chunk(0, 0);
    load_chunk(1, 1);

    for (int ch = 0; ch < KCHUNKS; ch++) {
        const int stg = ch % 3;
        if (ch >= KCHUNKS - 2) {
            asm volatile("cp.async.wait_group 0;" ::: "memory");
        } else {
            asm volatile("cp.async.wait_group 1;" ::: "memory");
        }
        __syncthreads();
        if (ch + 2 < KCHUNKS) load_chunk(ch + 2, (ch + 2) % 3);

        load_frags(stg, 0, 0);
        #pragma unroll
        for (int ks = 0; ks < 4; ks++) {
            if (ks < 3) load_frags(stg, ks + 1, (ks + 1) & 1);
            mma_step(ks & 1);
        }
        __syncthreads();   // all warps done with stage stg before it is overwritten
    }

    // ---- fused epilogue: theta=max(-d, 1+1e-7); out = -min(acosh(theta)^2, 50) ----
    const float THMIN = 1.00000011920928955f;  // fp32(1 + 1e-7), identical to jnp
    const float LN2 = 0.69314718055994531f;
    #pragma unroll
    for (int mi = 0; mi < 4; mi++) {
        const int r0 = m0 + mb + mi * 16 + (L >> 2);
        #pragma unroll
        for (int ni = 0; ni < 8; ni++) {
            const int col = n0 + nb + ni * 8 + (L & 3) * 2;
            float v[4];
            #pragma unroll
            for (int r = 0; r < 4; r++) {
                float th = fmaxf(-acc[mi][ni][r], THMIN);
                float x = fmaf(th, th, -1.0f);
                float sq; asm("sqrt.approx.f32 %0, %1;" : "=f"(sq) : "f"(x));
                float lg; asm("lg2.approx.f32 %0, %1;" : "=f"(lg) : "f"(th + sq));
                float s = lg * LN2;
                v[r] = -fminf(s * s, 50.0f);
            }
            *(float2*)(out + (size_t)r0 * NUM_ITEMS + col)       = make_float2(v[0], v[1]);
            *(float2*)(out + (size_t)(r0 + 8) * NUM_ITEMS + col) = make_float2(v[2], v[3]);
        }
    }
}

extern "C" void kernel_launch(void* const* d_in, const int* in_sizes, int n_in,
                              void* d_out, int out_size) {
    const float* h = (const float*)d_in[0];
    float* out = (float*)d_out;

    const int totPrep = (NUM_USERS + NUM_ITEMS) * KSEG + (NUM_USERS + NUM_ITEMS) * 16;
    prep_kernel<<<(totPrep + 255) / 256, 256>>>(h);

    cudaFuncSetAttribute(gemm_mma_kernel, cudaFuncAttributeMaxDynamicSharedMemorySize, SM_SIZE);
    dim3 grid(NUM_USERS / BM, NUM_ITEMS / BN);  // (64, 256)
    gemm_mma_kernel<<<grid, NTHREADS, SM_SIZE>>>(out);
}

// round 12
// speedup vs baseline: 1.3408x; 1.1114x over previous
#include <cuda_runtime.h>
#include <cuda_bf16.h>
#include <cstdint>
#include <math.h>

#define NUM_USERS 8192
#define NUM_ITEMS 32768
#define FEAT      129
#define KSEG      128              // features 0..127 in the GEMM; feature 128 peeled as rank-1
#define KCAT      384              // 3*KSEG exactly, zero padding waste
#define KCHUNKS   6
#define BM        128
#define BN        128
#define BK        64
#define NTHREADS  128              // 4 warps, each 64x64

// ---- scratch (__device__ globals: allocation-free) ----
__device__ __align__(128) __nv_bfloat16 g_Abf[(size_t)NUM_USERS * KCAT];  // [Ahi|Ahi|Alo]
__device__ __align__(128) __nv_bfloat16 g_Bbf[(size_t)NUM_ITEMS * KCAT];  // [Bhi|Blo|Bhi]
__device__ float g_A129[NUM_USERS];    // feature 128 of users (fp32, exact)
__device__ float g_B129[NUM_ITEMS];    // feature 128 of items (sign +1)

__device__ __forceinline__ uint32_t smem_u32(const void* p) {
    uint32_t a;
    asm("{ .reg .u64 t; cvta.to.shared.u64 t, %1; cvt.u32.u64 %0, t; }" : "=r"(a) : "l"(p));
    return a;
}

// ---- prep: fold sign, split fp32 -> (hi, lo) bf16, concatenated-K operands + rank-1 vectors ----
__global__ void prep_kernel(const float* __restrict__ h) {
    int idx = blockIdx.x * blockDim.x + threadIdx.x;
    const int totA = NUM_USERS * KSEG;
    const int totB = NUM_ITEMS * KSEG;
    if (idx < totA) {
        int u = idx >> 7, k = idx & 127;
        float a = h[(size_t)u * FEAT + k];
        __nv_bfloat16 hi = __float2bfloat16(a);
        __nv_bfloat16 lo = __float2bfloat16(a - __bfloat162float(hi));
        __nv_bfloat16* row = g_Abf + (size_t)u * KCAT;
        row[k] = hi; row[KSEG + k] = hi; row[2 * KSEG + k] = lo;
    } else if (idx < totA + totB) {
        int j = idx - totA;
        int i = j >> 7, k = j & 127;
        float b = h[(size_t)(NUM_USERS + i) * FEAT + k];
        if (k == 0) b = -b;  // sign fold (signs[0] = -1)
        __nv_bfloat16 hi = __float2bfloat16(b);
        __nv_bfloat16 lo = __float2bfloat16(b - __bfloat162float(hi));
        __nv_bfloat16* row = g_Bbf + (size_t)i * KCAT;
        row[k] = hi; row[KSEG + k] = lo; row[2 * KSEG + k] = hi;
    } else if (idx < totA + totB + NUM_USERS) {
        int u = idx - totA - totB;
        g_A129[u] = h[(size_t)u * FEAT + 128];
    } else if (idx < totA + totB + NUM_USERS + NUM_ITEMS) {
        int i = idx - totA - totB - NUM_USERS;
        g_B129[i] = h[(size_t)(NUM_USERS + i) * FEAT + 128];
    }
}

// smem: 3 stages x (A 16KB + B 16KB) + 1KB rank-1 vectors = 99328 (2 CTAs/SM ok)
#define ST_BYTES  32768
#define SB_OFF    16384
#define SA129_OFF 98304
#define SB129_OFF 98816
#define SM_SIZE   99328

__global__ __launch_bounds__(NTHREADS, 2)
void gemm_mma_kernel(float* __restrict__ out) {
    extern __shared__ __align__(1024) char smem[];
    const uint32_t sb = smem_u32(smem);
    const int tid = threadIdx.x;
    const int wid = tid >> 5;
    const int L = tid & 31;
    const int m0 = blockIdx.x * BM;
    const int n0 = blockIdx.y * BN;
    const int mb = (wid & 1) * 64;    // 2 warps in m
    const int nb = (wid >> 1) * 64;   // 2 warps in n

    float* sA129 = (float*)(smem + SA129_OFF);
    float* sB129 = (float*)(smem + SB129_OFF);
    sA129[tid] = g_A129[m0 + tid];    // 128 threads, 128 values each
    sB129[tid] = g_B129[n0 + tid];

    float acc[4][8][4];               // 128 fp32 accum per lane (64x64 warp tile)
    #pragma unroll
    for (int mi = 0; mi < 4; mi++)
        #pragma unroll
        for (int ni = 0; ni < 8; ni++)
            #pragma unroll
            for (int r = 0; r < 4; r++) acc[mi][ni][r] = 0.0f;

    // per-lane ldmatrix addressing (SW128 swizzle: XOR = (row&7)*16)
    const uint32_t xorv = (L & 7) * 16;
    const uint32_t kha = (L >> 4) * 16;          // A: k-half select from lane
    const uint32_t khb = ((L >> 3) & 1) * 16;    // B: k-half select from lane
    uint32_t aBase[4], bBase[4];
    #pragma unroll
    for (int mi = 0; mi < 4; mi++)
        aBase[mi] = (uint32_t)(mb + mi * 16 + (L & 7) + ((L >> 3) & 1) * 8) * 128;
    #pragma unroll
    for (int p = 0; p < 4; p++)
        bBase[p] = (uint32_t)(nb + p * 16 + (L & 7) + ((L >> 4) & 1) * 8) * 128;

    // cooperative cp.async chunk loader (64 bf16 K-cols; A 128 rows, B 128 rows)
    auto load_chunk = [&](int c, int stg) {
        const uint32_t base = sb + stg * ST_BYTES;
        const size_t kbase = (size_t)c * BK;
        #pragma unroll
        for (int it = 0; it < 8; it++) {                 // A: 1024 x 16B
            int idx = tid + it * NTHREADS;
            int row = idx >> 3, k8 = idx & 7;
            const void* src = g_Abf + (size_t)(m0 + row) * KCAT + kbase + k8 * 8;
            uint32_t off = row * 128 + k8 * 16;
            uint32_t dst = base + (off ^ ((off >> 3) & 0x70));
            asm volatile("cp.async.cg.shared.global [%0], [%1], 16;" :: "r"(dst), "l"(src));
        }
        #pragma unroll
        for (int it = 0; it < 8; it++) {                 // B: 1024 x 16B
            int idx = tid + it * NTHREADS;
            int row = idx >> 3, k8 = idx & 7;
            const void* src = g_Bbf + (size_t)(n0 + row) * KCAT + kbase + k8 * 8;
            uint32_t off = row * 128 + k8 * 16;
            uint32_t dst = base + SB_OFF + (off ^ ((off >> 3) & 0x70));
            asm volatile("cp.async.cg.shared.global [%0], [%1], 16;" :: "r"(dst), "l"(src));
        }
        asm volatile("cp.async.commit_group;" ::: "memory");
    };

    // fragment buffers (double-buffered across k16 steps)
    uint32_t af[2][4][4], bf[2][4][4];
    auto load_frags = [&](int stg, int ks, int buf) {
        const uint32_t stA = sb + stg * ST_BYTES;
        const uint32_t stB = stA + SB_OFF;
        #pragma unroll
        for (int mi = 0; mi < 4; mi++) {
            uint32_t addr = stA + aBase[mi] + (((uint32_t)ks * 32 + kha) ^ xorv);
            asm volatile("ldmatrix.sync.aligned.m8n8.x4.shared.b16 {%0,%1,%2,%3}, [%4];"
                : "=r"(af[buf][mi][0]), "=r"(af[buf][mi][1]),
                  "=r"(af[buf][mi][2]), "=r"(af[buf][mi][3]) : "r"(addr));
        }
        #pragma unroll
        for (int p = 0; p < 4; p++) {
            uint32_t addr = stB + bBase[p] + (((uint32_t)ks * 32 + khb) ^ xorv);
            asm volatile("ldmatrix.sync.aligned.m8n8.x4.shared.b16 {%0,%1,%2,%3}, [%4];"
                : "=r"(bf[buf][p][0]), "=r"(bf[buf][p][1]),
                  "=r"(bf[buf][p][2]), "=r"(bf[buf][p][3]) : "r"(addr));
        }
    };
    auto mma_step = [&](int buf) {
        #pragma unroll
        for (int mi = 0; mi < 4; mi++)
            #pragma unroll
            for (int ni = 0; ni < 8; ni++) {
                const uint32_t* bb = &bf[buf][ni >> 1][(ni & 1) * 2];
                asm volatile(
                    "mma.sync.aligned.m16n8k16.row.col.f32.bf16.bf16.f32 "
                    "{%0,%1,%2,%3}, {%4,%5,%6,%7}, {%8,%9}, {%0,%1,%2,%3};"
                    : "+f"(acc[mi][ni][0]), "+f"(acc[mi][ni][1]),
                      "+f"(acc[mi][ni][2]), "+f"(acc[mi][ni][3])
                    : "r"(af[buf][mi][0]), "r"(af[buf][mi][1]),
                      "r"(af[buf][mi][2]), "r"(af[buf][mi][3]),
                      "r"(bb[0]), "r"(bb[1]));
            }
    };

    // 3-stage pipeline prologue
    load_chunk(0, 0);
    load_chunk(1, 1);

    for (int ch = 0; ch < KCHUNKS; ch++) {
        const int stg = ch % 3;
        if (ch >= KCHUNKS - 2) {
            asm volatile("cp.async.wait_group 0;" ::: "memory");
        } else {
            asm volatile("cp.async.wait_group 1;" ::: "memory");
        }
        __syncthreads();   // also protects stage (ch%3) from iteration ch+1's overwrite
        if (ch + 2 < KCHUNKS) load_chunk(ch + 2, (ch + 2) % 3);

        load_frags(stg, 0, 0);
        #pragma unroll
        for (int ks = 0; ks < 4; ks++) {
            if (ks < 3) load_frags(stg, ks + 1, (ks + 1) & 1);
            mma_step(ks & 1);
        }
        // no end-of-loop sync: next iteration's top sync orders reuse
    }

    // ---- fused epilogue: dot = MMA + a129*b129 (exact fp32 rank-1 peel) ----
    const float THMIN = 1.00000011920928955f;  // fp32(1 + 1e-7), identical to jnp
    const float LN2 = 0.69314718055994531f;
    #pragma unroll
    for (int mi = 0; mi < 4; mi++) {
        const int r0 = m0 + mb + mi * 16 + (L >> 2);
        const float am0 = sA129[mb + mi * 16 + (L >> 2)];
        const float am8 = sA129[mb + mi * 16 + (L >> 2) + 8];
        #pragma unroll
        for (int ni = 0; ni < 8; ni++) {
            const int col = n0 + nb + ni * 8 + (L & 3) * 2;
            const float bc0 = sB129[nb + ni * 8 + (L & 3) * 2];
            const float bc1 = sB129[nb + ni * 8 + (L & 3) * 2 + 1];
            float v[4];
            const float am[4] = {am0, am0, am8, am8};
            const float bc[4] = {bc0, bc1, bc0, bc1};
            #pragma unroll
            for (int r = 0; r < 4; r++) {
                float th = fmaxf(fmaf(-am[r], bc[r], -acc[mi][ni][r]), THMIN);
                float x = fmaf(th, th, -1.0f);
                float sq; asm("sqrt.approx.f32 %0, %1;" : "=f"(sq) : "f"(x));
                float lg; asm("lg2.approx.f32 %0, %1;" : "=f"(lg) : "f"(th + sq));
                float s = lg * LN2;
                v[r] = -fminf(s * s, 50.0f);
            }
            *(float2*)(out + (size_t)r0 * NUM_ITEMS + col)       = make_float2(v[0], v[1]);
            *(float2*)(out + (size_t)(r0 + 8) * NUM_ITEMS + col) = make_float2(v[2], v[3]);
        }
    }
}

extern "C" void kernel_launch(void* const* d_in, const int* in_sizes, int n_in,
                              void* d_out, int out_size) {
    const float* h = (const float*)d_in[0];
    float* out = (float*)d_out;

    const int totPrep = (NUM_USERS + NUM_ITEMS) * KSEG + NUM_USERS + NUM_ITEMS;
    prep_kernel<<<(totPrep + 255) / 256, 256>>>(h);

    cudaFuncSetAttribute(gemm_mma_kernel, cudaFuncAttributeMaxDynamicSharedMemorySize, SM_SIZE);
    dim3 grid(NUM_USERS / BM, NUM_ITEMS / BN);  // (64, 256)
    gemm_mma_kernel<<<grid, NTHREADS, SM_SIZE>>>(out);
}